// round 15
// baseline (speedup 1.0000x reference)
#include <cuda_runtime.h>
#include <cuda_bf16.h>
#include <cstdint>

typedef unsigned long long u64;

// ---------------- constants ----------------
#define NHEAD 8
#define DH 32
#define BLOCK 8
#define HALO 3
#define WIN 14          // BLOCK + 2*HALO
#define KK 196          // WIN*WIN
#define QN 64           // BLOCK*BLOCK
#define NBS 16          // blocks per side (128/8)
#define NBLK 256        // NBS*NBS
#define HW 16384        // 128*128
#define SCALE 0.17677669529663688f

// scratch: q in attention layout [b*8+head][blk][qp][d]
__device__ float g_q[4 * 8 * NBLK * QN * DH];          // 16.78M floats
// kv in spatial-major layout [b][y][x][ch512]; head h: k=ch[64h..64h+32), v=ch[64h+32..64h+64)
__device__ float g_kv[4 * 128 * 128 * 512];            // 33.55M floats

// ---------------- f32x2 helpers ----------------
__device__ __forceinline__ u64 pack2(float lo, float hi) {
    u64 r; asm("mov.b64 %0,{%1,%2};" : "=l"(r) : "f"(lo), "f"(hi)); return r;
}
__device__ __forceinline__ void fma2(u64& d, u64 a, u64 b) {
    asm("fma.rn.f32x2 %0,%1,%2,%0;" : "+l"(d) : "l"(a), "l"(b));
}
__device__ __forceinline__ float2 unpack2(u64 v) {
    float2 f; asm("mov.b64 {%0,%1},%2;" : "=f"(f.x), "=f"(f.y) : "l"(v)); return f;
}

// =========================================================================
// Kernel 1: fused QKV projection.  Y[768,16384] = W[768,256] @ X[256,16384]
// per batch.  Tile: 64 (o) x 128 (s), 256 threads, thread tile 8x4.
// =========================================================================
__global__ __launch_bounds__(256) void qkv_gemm(
    const float* __restrict__ x,
    const float* __restrict__ wq,
    const float* __restrict__ wkv)
{
    __shared__ float As[16][68];     // [k][o], padded
    __shared__ float Bs[16][128];    // [k][s]

    const int b      = blockIdx.z;
    const int tile_o = blockIdx.y * 64;
    const int tile_s = blockIdx.x * 128;
    const int tid    = threadIdx.x;
    const int tx     = tid & 31;     // s dir
    const int ty     = tid >> 5;     // o dir (warp id)

    // A-load mapping: 64 rows x 16 cols per tile
    const int arow = tid >> 2;              // 0..63
    const int acol = (tid & 3) << 2;        // 0,4,8,12
    const int oa   = tile_o + arow;
    const float* wrow = (oa < 256) ? (wq + (size_t)oa * 256)
                                   : (wkv + (size_t)(oa - 256) * 256);
    // B-load mapping: 16 rows x 128 cols
    const int brow = tid >> 4;              // 0..15
    const int bcol = (tid & 15) << 3;       // 0..120 step 8
    const float* xbase = x + ((size_t)b * 256 + brow) * HW + tile_s + bcol;

    u64 acc[4][4];
    #pragma unroll
    for (int i = 0; i < 4; i++)
        #pragma unroll
        for (int j = 0; j < 4; j++) acc[i][j] = 0ULL;

    for (int kt = 0; kt < 256; kt += 16) {
        float4 av = *(const float4*)(wrow + kt + acol);
        As[acol + 0][arow] = av.x;
        As[acol + 1][arow] = av.y;
        As[acol + 2][arow] = av.z;
        As[acol + 3][arow] = av.w;
        const float* xp = xbase + (size_t)kt * HW;
        float4 b0 = *(const float4*)(xp);
        float4 b1 = *(const float4*)(xp + 4);
        *(float4*)&Bs[brow][bcol]     = b0;
        *(float4*)&Bs[brow][bcol + 4] = b1;
        __syncthreads();

        #pragma unroll
        for (int k = 0; k < 16; k++) {
            const u64* a2 = (const u64*)&As[k][ty << 3];  // 16B-aligned (272B row stride)
            u64 A0 = a2[0], A1 = a2[1], A2 = a2[2], A3 = a2[3];
            float4 bv = *(const float4*)&Bs[k][tx << 2];
            u64 B0 = pack2(bv.x, bv.x);
            u64 B1 = pack2(bv.y, bv.y);
            u64 B2 = pack2(bv.z, bv.z);
            u64 B3 = pack2(bv.w, bv.w);
            fma2(acc[0][0], A0, B0); fma2(acc[1][0], A1, B0); fma2(acc[2][0], A2, B0); fma2(acc[3][0], A3, B0);
            fma2(acc[0][1], A0, B1); fma2(acc[1][1], A1, B1); fma2(acc[2][1], A2, B1); fma2(acc[3][1], A3, B1);
            fma2(acc[0][2], A0, B2); fma2(acc[1][2], A1, B2); fma2(acc[2][2], A2, B2); fma2(acc[3][2], A3, B2);
            fma2(acc[0][3], A0, B3); fma2(acc[1][3], A1, B3); fma2(acc[2][3], A2, B3); fma2(acc[3][3], A3, B3);
        }
        __syncthreads();
    }

    // epilogue: thread owns o = o0..o0+7 (within one head), s = s0..s0+3
    const int o0 = tile_o + (ty << 3);
    const int s0 = tile_s + (tx << 2);
    #pragma unroll
    for (int j = 0; j < 4; j++) {
        const int s = s0 + j;
        const int y = s >> 7, xx = s & 127;
        float2 f0 = unpack2(acc[0][j]);
        float2 f1 = unpack2(acc[1][j]);
        float2 f2 = unpack2(acc[2][j]);
        float2 f3 = unpack2(acc[3][j]);
        float4 lo = make_float4(f0.x, f0.y, f1.x, f1.y);
        float4 hi = make_float4(f2.x, f2.y, f3.x, f3.y);
        if (tile_o < 256) {
            const int head = o0 >> 5, d0 = o0 & 31;
            const int blkq = ((y >> 3) << 4) + (xx >> 3);
            const int qp   = ((y & 7) << 3) + (xx & 7);
            float* dst = g_q + ((((size_t)(b * 8 + head) * NBLK + blkq) << 6) + qp) * 32 + d0;
            *(float4*)dst       = lo;
            *(float4*)(dst + 4) = hi;
        } else {
            const int oc = o0 - 256;
            float* dst = g_kv + (((size_t)(b * 128 + y) * 128 + xx) << 9) + oc;
            *(float4*)dst       = lo;
            *(float4*)(dst + 4) = hi;
        }
    }
}

// =========================================================================
// Kernel 2: halo attention. One CTA per (b, head, block). 256 threads.
// =========================================================================
#define SMEM_FLOATS 33552
#define SMEM_BYTES  (SMEM_FLOATS * 4)

__global__ __launch_bounds__(256) void attn_kernel(
    const float* __restrict__ hrel,
    const float* __restrict__ wrel,
    float* __restrict__ out)
{
    extern __shared__ float sm[];
    float* qs = sm;            // 64 x 34   (stride 34 -> 8B aligned rows, conflict-free)
    float* ks = qs + 2176;     // 196 x 34
    float* vs = ks + 6664;     // 196 x 34
    float* P  = vs + 6664;     // 64 x 197  (stride 197 -> conflict-free scatter)
    float* qh = P  + 12608;    // 64 x 27
    float* qw = qh + 1728;     // 64 x 27
    float* sh = qw + 1728;     // 27 x 32
    float* sw = sh + 864;      // 27 x 32
    float* red = sw + 864;     // 256

    const int b = blockIdx.z, head = blockIdx.y, blk = blockIdx.x;
    const int tid = threadIdx.x;
    const int blky = blk >> 4, blkx = blk & 15;

    // ---- load q tile (contiguous 8KB) ----
    const float* qg = g_q + (((size_t)(b * 8 + head) * NBLK + blk) << 11);
    for (int i = tid; i < 2048; i += 256)
        qs[(i >> 5) * 34 + (i & 31)] = qg[i];
    // ---- rel tables ----
    for (int i = tid; i < 864; i += 256) { sh[i] = hrel[i]; sw[i] = wrel[i]; }
    // ---- gather K/V window (256B contiguous per position, zero halo OOB) ----
    const int y0 = blky * 8 - HALO, x0 = blkx * 8 - HALO;
    const float* kvb = g_kv + (size_t)b * 128 * 128 * 512 + head * 64;
    for (int i = tid; i < KK * 64; i += 256) {
        const int pos = i >> 6, ch = i & 63;
        const int kr = pos / 14, kc = pos - kr * 14;
        const int yy = y0 + kr, xx = x0 + kc;
        float v = 0.f;
        if ((unsigned)yy < 128u && (unsigned)xx < 128u)
            v = kvb[(((size_t)yy << 7) + xx) * 512 + ch];
        if (ch < 32) ks[pos * 34 + ch] = v;
        else         vs[pos * 34 + ch - 32] = v;
    }
    __syncthreads();

    // ---- rel-pos projections qh[qp][idx] = q . height_rel[idx], qw likewise ----
    for (int i = tid; i < 64 * 54; i += 256) {
        const int qp = i / 54, rr = i - qp * 54;
        const float* rel = (rr < 27) ? (sh + rr * 32) : (sw + (rr - 27) * 32);
        const float* qr = qs + qp * 34;
        float a = 0.f;
        #pragma unroll
        for (int d = 0; d < 32; d++) a += qr[d] * rel[d];
        if (rr < 27) qh[qp * 27 + rr] = a;
        else         qw[qp * 27 + rr - 27] = a;
    }
    __syncthreads();

    // ---- logits: thread = (qp, k-chunk of 49) ----
    {
        const int qp = tid & 63, chunk = tid >> 6;
        const int r = qp >> 3, c = qp & 7;
        const u64* q2 = (const u64*)(qs + qp * 34);
        u64 qa[16];
        #pragma unroll
        for (int j = 0; j < 16; j++) qa[j] = q2[j];
        const float* qhr = qh + qp * 27 + (13 - r);
        const float* qwr = qw + qp * 27 + (13 - c);
        float* prow = P + qp * 197;
        for (int kk = chunk; kk < KK; kk += 4) {
            const int kr = kk / 14, kc = kk - kr * 14;
            const u64* k2 = (const u64*)(ks + kk * 34);  // broadcast within warp
            u64 a0 = 0ULL, a1 = 0ULL, a2 = 0ULL, a3 = 0ULL;
            #pragma unroll
            for (int j = 0; j < 16; j += 4) {
                fma2(a0, qa[j],     k2[j]);
                fma2(a1, qa[j + 1], k2[j + 1]);
                fma2(a2, qa[j + 2], k2[j + 2]);
                fma2(a3, qa[j + 3], k2[j + 3]);
            }
            float2 f0 = unpack2(a0), f1 = unpack2(a1), f2 = unpack2(a2), f3 = unpack2(a3);
            const float dot = ((f0.x + f0.y) + (f1.x + f1.y)) + ((f2.x + f2.y) + (f3.x + f3.y));
            prow[kk] = dot * SCALE + qhr[kr] + qwr[kc];
        }
    }
    __syncthreads();

    // ---- softmax: 4 threads per q row, 49 keys each ----
    const int qpS = tid >> 2, q4 = tid & 3;
    {
        float* pr = P + qpS * 197 + q4 * 49;
        float m = -1e30f;
        for (int j = 0; j < 49; j++) m = fmaxf(m, pr[j]);
        red[tid] = m;
        __syncthreads();
        const float mm = fmaxf(fmaxf(red[qpS * 4], red[qpS * 4 + 1]),
                               fmaxf(red[qpS * 4 + 2], red[qpS * 4 + 3]));
        __syncthreads();
        float s = 0.f;
        for (int j = 0; j < 49; j++) { float e = __expf(pr[j] - mm); pr[j] = e; s += e; }
        red[tid] = s;
        __syncthreads();
    }
    const float denom = red[qpS * 4] + red[qpS * 4 + 1] + red[qpS * 4 + 2] + red[qpS * 4 + 3];
    const float inv = 1.0f / denom;

    // ---- AV: thread = (q row, 8 dv channels) ----
    {
        const int dv0 = q4 << 3;
        const float* pr = P + qpS * 197;
        u64 acc0 = 0ULL, acc1 = 0ULL, acc2 = 0ULL, acc3 = 0ULL;
        #pragma unroll 4
        for (int j = 0; j < KK; j++) {
            const float p = pr[j];
            const u64 p2 = pack2(p, p);
            const u64* vr = (const u64*)(vs + j * 34 + dv0);
            fma2(acc0, p2, vr[0]);
            fma2(acc1, p2, vr[1]);
            fma2(acc2, p2, vr[2]);
            fma2(acc3, p2, vr[3]);
        }
        const int rr = qpS >> 3, cc = qpS & 7;
        const int y = blky * 8 + rr, x = blkx * 8 + cc;
        float* ob = out + (((size_t)(b * 256) + head * 32 + dv0) * 128 + y) * 128 + x;
        float2 g;
        g = unpack2(acc0); ob[0]         = g.x * inv; ob[(size_t)1 * HW] = g.y * inv;
        g = unpack2(acc1); ob[(size_t)2 * HW] = g.x * inv; ob[(size_t)3 * HW] = g.y * inv;
        g = unpack2(acc2); ob[(size_t)4 * HW] = g.x * inv; ob[(size_t)5 * HW] = g.y * inv;
        g = unpack2(acc3); ob[(size_t)6 * HW] = g.x * inv; ob[(size_t)7 * HW] = g.y * inv;
    }
}

// =========================================================================
extern "C" void kernel_launch(void* const* d_in, const int* in_sizes, int n_in,
                              void* d_out, int out_size)
{
    (void)in_sizes; (void)n_in; (void)out_size;
    const float* x    = (const float*)d_in[0];
    const float* wq   = (const float*)d_in[1];
    const float* wkv  = (const float*)d_in[2];
    const float* hrel = (const float*)d_in[3];
    const float* wrel = (const float*)d_in[4];
    float* out = (float*)d_out;

    cudaFuncSetAttribute(attn_kernel, cudaFuncAttributeMaxDynamicSharedMemorySize, SMEM_BYTES);

    qkv_gemm<<<dim3(128, 12, 4), 256>>>(x, wq, wkv);
    attn_kernel<<<dim3(NBLK, NHEAD, 4), 256, SMEM_BYTES>>>(hrel, wrel, out);
}

// round 16
// speedup vs baseline: 1.0004x; 1.0004x over previous
#include <cuda_runtime.h>
#include <cuda_bf16.h>
#include <cstdint>

typedef unsigned long long u64;

// ---------------- constants ----------------
#define NHEAD 8
#define DH 32
#define BLOCK 8
#define HALO 3
#define WIN 14          // BLOCK + 2*HALO
#define KK 196          // WIN*WIN
#define QN 64           // BLOCK*BLOCK
#define NBS 16          // blocks per side (128/8)
#define NBLK 256        // NBS*NBS
#define HW 16384        // 128*128
#define SCALE 0.17677669529663688f

// scratch: q in attention layout [b*8+head][blk][qp][d]
__device__ float g_q[4 * 8 * NBLK * QN * DH];          // 16.78M floats
// kv in spatial-major layout [b][y][x][ch512]; head h: k=ch[64h..64h+32), v=ch[64h+32..64h+64)
__device__ float g_kv[4 * 128 * 128 * 512];            // 33.55M floats

// ---------------- f32x2 helpers ----------------
__device__ __forceinline__ u64 pack2(float lo, float hi) {
    u64 r; asm("mov.b64 %0,{%1,%2};" : "=l"(r) : "f"(lo), "f"(hi)); return r;
}
__device__ __forceinline__ void fma2(u64& d, u64 a, u64 b) {
    asm("fma.rn.f32x2 %0,%1,%2,%0;" : "+l"(d) : "l"(a), "l"(b));
}
__device__ __forceinline__ float2 unpack2(u64 v) {
    float2 f; asm("mov.b64 {%0,%1},%2;" : "=f"(f.x), "=f"(f.y) : "l"(v)); return f;
}

// =========================================================================
// Kernel 1: fused QKV projection.  Y[768,16384] = W[768,256] @ X[256,16384]
// per batch.  Tile: 64 (o) x 128 (s), 256 threads, thread tile 8x4.
// =========================================================================
__global__ __launch_bounds__(256) void qkv_gemm(
    const float* __restrict__ x,
    const float* __restrict__ wq,
    const float* __restrict__ wkv)
{
    __shared__ float As[16][68];     // [k][o], padded
    __shared__ float Bs[16][128];    // [k][s]

    const int b      = blockIdx.z;
    const int tile_o = blockIdx.y * 64;
    const int tile_s = blockIdx.x * 128;
    const int tid    = threadIdx.x;
    const int tx     = tid & 31;     // s dir
    const int ty     = tid >> 5;     // o dir (warp id)

    // A-load mapping: 64 rows x 16 cols per tile
    const int arow = tid >> 2;              // 0..63
    const int acol = (tid & 3) << 2;        // 0,4,8,12
    const int oa   = tile_o + arow;
    const float* wrow = (oa < 256) ? (wq + (size_t)oa * 256)
                                   : (wkv + (size_t)(oa - 256) * 256);
    // B-load mapping: 16 rows x 128 cols
    const int brow = tid >> 4;              // 0..15
    const int bcol = (tid & 15) << 3;       // 0..120 step 8
    const float* xbase = x + ((size_t)b * 256 + brow) * HW + tile_s + bcol;

    u64 acc[4][4];
    #pragma unroll
    for (int i = 0; i < 4; i++)
        #pragma unroll
        for (int j = 0; j < 4; j++) acc[i][j] = 0ULL;

    for (int kt = 0; kt < 256; kt += 16) {
        float4 av = *(const float4*)(wrow + kt + acol);
        As[acol + 0][arow] = av.x;
        As[acol + 1][arow] = av.y;
        As[acol + 2][arow] = av.z;
        As[acol + 3][arow] = av.w;
        const float* xp = xbase + (size_t)kt * HW;
        float4 b0 = *(const float4*)(xp);
        float4 b1 = *(const float4*)(xp + 4);
        *(float4*)&Bs[brow][bcol]     = b0;
        *(float4*)&Bs[brow][bcol + 4] = b1;
        __syncthreads();

        #pragma unroll
        for (int k = 0; k < 16; k++) {
            const u64* a2 = (const u64*)&As[k][ty << 3];  // 16B-aligned (272B row stride)
            u64 A0 = a2[0], A1 = a2[1], A2 = a2[2], A3 = a2[3];
            float4 bv = *(const float4*)&Bs[k][tx << 2];
            u64 B0 = pack2(bv.x, bv.x);
            u64 B1 = pack2(bv.y, bv.y);
            u64 B2 = pack2(bv.z, bv.z);
            u64 B3 = pack2(bv.w, bv.w);
            fma2(acc[0][0], A0, B0); fma2(acc[1][0], A1, B0); fma2(acc[2][0], A2, B0); fma2(acc[3][0], A3, B0);
            fma2(acc[0][1], A0, B1); fma2(acc[1][1], A1, B1); fma2(acc[2][1], A2, B1); fma2(acc[3][1], A3, B1);
            fma2(acc[0][2], A0, B2); fma2(acc[1][2], A1, B2); fma2(acc[2][2], A2, B2); fma2(acc[3][2], A3, B2);
            fma2(acc[0][3], A0, B3); fma2(acc[1][3], A1, B3); fma2(acc[2][3], A2, B3); fma2(acc[3][3], A3, B3);
        }
        __syncthreads();
    }

    // epilogue: thread owns o = o0..o0+7 (within one head), s = s0..s0+3
    const int o0 = tile_o + (ty << 3);
    const int s0 = tile_s + (tx << 2);
    #pragma unroll
    for (int j = 0; j < 4; j++) {
        const int s = s0 + j;
        const int y = s >> 7, xx = s & 127;
        float2 f0 = unpack2(acc[0][j]);
        float2 f1 = unpack2(acc[1][j]);
        float2 f2 = unpack2(acc[2][j]);
        float2 f3 = unpack2(acc[3][j]);
        float4 lo = make_float4(f0.x, f0.y, f1.x, f1.y);
        float4 hi = make_float4(f2.x, f2.y, f3.x, f3.y);
        if (tile_o < 256) {
            const int head = o0 >> 5, d0 = o0 & 31;
            const int blkq = ((y >> 3) << 4) + (xx >> 3);
            const int qp   = ((y & 7) << 3) + (xx & 7);
            float* dst = g_q + ((((size_t)(b * 8 + head) * NBLK + blkq) << 6) + qp) * 32 + d0;
            *(float4*)dst       = lo;
            *(float4*)(dst + 4) = hi;
        } else {
            const int oc = o0 - 256;
            float* dst = g_kv + (((size_t)(b * 128 + y) * 128 + xx) << 9) + oc;
            *(float4*)dst       = lo;
            *(float4*)(dst + 4) = hi;
        }
    }
}

// =========================================================================
// Kernel 2: halo attention. One CTA per (b, head, block). 256 threads.
// =========================================================================
#define SMEM_FLOATS 33552
#define SMEM_BYTES  (SMEM_FLOATS * 4)

__global__ __launch_bounds__(256) void attn_kernel(
    const float* __restrict__ hrel,
    const float* __restrict__ wrel,
    float* __restrict__ out)
{
    extern __shared__ float sm[];
    float* qs = sm;            // 64 x 34   (stride 34 -> 8B aligned rows, conflict-free)
    float* ks = qs + 2176;     // 196 x 34
    float* vs = ks + 6664;     // 196 x 34
    float* P  = vs + 6664;     // 64 x 197  (stride 197 -> conflict-free scatter)
    float* qh = P  + 12608;    // 64 x 27
    float* qw = qh + 1728;     // 64 x 27
    float* sh = qw + 1728;     // 27 x 32
    float* sw = sh + 864;      // 27 x 32
    float* red = sw + 864;     // 256

    const int b = blockIdx.z, head = blockIdx.y, blk = blockIdx.x;
    const int tid = threadIdx.x;
    const int blky = blk >> 4, blkx = blk & 15;

    // ---- load q tile (contiguous 8KB) ----
    const float* qg = g_q + (((size_t)(b * 8 + head) * NBLK + blk) << 11);
    for (int i = tid; i < 2048; i += 256)
        qs[(i >> 5) * 34 + (i & 31)] = qg[i];
    // ---- rel tables ----
    for (int i = tid; i < 864; i += 256) { sh[i] = hrel[i]; sw[i] = wrel[i]; }
    // ---- gather K/V window (256B contiguous per position, zero halo OOB) ----
    const int y0 = blky * 8 - HALO, x0 = blkx * 8 - HALO;
    const float* kvb = g_kv + (size_t)b * 128 * 128 * 512 + head * 64;
    for (int i = tid; i < KK * 64; i += 256) {
        const int pos = i >> 6, ch = i & 63;
        const int kr = pos / 14, kc = pos - kr * 14;
        const int yy = y0 + kr, xx = x0 + kc;
        float v = 0.f;
        if ((unsigned)yy < 128u && (unsigned)xx < 128u)
            v = kvb[(((size_t)yy << 7) + xx) * 512 + ch];
        if (ch < 32) ks[pos * 34 + ch] = v;
        else         vs[pos * 34 + ch - 32] = v;
    }
    __syncthreads();

    // ---- rel-pos projections qh[qp][idx] = q . height_rel[idx], qw likewise ----
    for (int i = tid; i < 64 * 54; i += 256) {
        const int qp = i / 54, rr = i - qp * 54;
        const float* rel = (rr < 27) ? (sh + rr * 32) : (sw + (rr - 27) * 32);
        const float* qr = qs + qp * 34;
        float a = 0.f;
        #pragma unroll
        for (int d = 0; d < 32; d++) a += qr[d] * rel[d];
        if (rr < 27) qh[qp * 27 + rr] = a;
        else         qw[qp * 27 + rr - 27] = a;
    }
    __syncthreads();

    // ---- logits: thread = (qp, k-chunk of 49) ----
    {
        const int qp = tid & 63, chunk = tid >> 6;
        const int r = qp >> 3, c = qp & 7;
        const u64* q2 = (const u64*)(qs + qp * 34);
        u64 qa[16];
        #pragma unroll
        for (int j = 0; j < 16; j++) qa[j] = q2[j];
        const float* qhr = qh + qp * 27 + (13 - r);
        const float* qwr = qw + qp * 27 + (13 - c);
        float* prow = P + qp * 197;
        for (int kk = chunk; kk < KK; kk += 4) {
            const int kr = kk / 14, kc = kk - kr * 14;
            const u64* k2 = (const u64*)(ks + kk * 34);  // broadcast within warp
            u64 a0 = 0ULL, a1 = 0ULL, a2 = 0ULL, a3 = 0ULL;
            #pragma unroll
            for (int j = 0; j < 16; j += 4) {
                fma2(a0, qa[j],     k2[j]);
                fma2(a1, qa[j + 1], k2[j + 1]);
                fma2(a2, qa[j + 2], k2[j + 2]);
                fma2(a3, qa[j + 3], k2[j + 3]);
            }
            float2 f0 = unpack2(a0), f1 = unpack2(a1), f2 = unpack2(a2), f3 = unpack2(a3);
            const float dot = ((f0.x + f0.y) + (f1.x + f1.y)) + ((f2.x + f2.y) + (f3.x + f3.y));
            prow[kk] = dot * SCALE + qhr[kr] + qwr[kc];
        }
    }
    __syncthreads();

    // ---- softmax: 4 threads per q row, 49 keys each ----
    const int qpS = tid >> 2, q4 = tid & 3;
    {
        float* pr = P + qpS * 197 + q4 * 49;
        float m = -1e30f;
        for (int j = 0; j < 49; j++) m = fmaxf(m, pr[j]);
        red[tid] = m;
        __syncthreads();
        const float mm = fmaxf(fmaxf(red[qpS * 4], red[qpS * 4 + 1]),
                               fmaxf(red[qpS * 4 + 2], red[qpS * 4 + 3]));
        __syncthreads();
        float s = 0.f;
        for (int j = 0; j < 49; j++) { float e = __expf(pr[j] - mm); pr[j] = e; s += e; }
        red[tid] = s;
        __syncthreads();
    }
    const float denom = red[qpS * 4] + red[qpS * 4 + 1] + red[qpS * 4 + 2] + red[qpS * 4 + 3];
    const float inv = 1.0f / denom;

    // ---- AV: thread = (q row, 8 dv channels) ----
    {
        const int dv0 = q4 << 3;
        const float* pr = P + qpS * 197;
        u64 acc0 = 0ULL, acc1 = 0ULL, acc2 = 0ULL, acc3 = 0ULL;
        #pragma unroll 4
        for (int j = 0; j < KK; j++) {
            const float p = pr[j];
            const u64 p2 = pack2(p, p);
            const u64* vr = (const u64*)(vs + j * 34 + dv0);
            fma2(acc0, p2, vr[0]);
            fma2(acc1, p2, vr[1]);
            fma2(acc2, p2, vr[2]);
            fma2(acc3, p2, vr[3]);
        }
        const int rr = qpS >> 3, cc = qpS & 7;
        const int y = blky * 8 + rr, x = blkx * 8 + cc;
        float* ob = out + (((size_t)(b * 256) + head * 32 + dv0) * 128 + y) * 128 + x;
        float2 g;
        g = unpack2(acc0); ob[0]         = g.x * inv; ob[(size_t)1 * HW] = g.y * inv;
        g = unpack2(acc1); ob[(size_t)2 * HW] = g.x * inv; ob[(size_t)3 * HW] = g.y * inv;
        g = unpack2(acc2); ob[(size_t)4 * HW] = g.x * inv; ob[(size_t)5 * HW] = g.y * inv;
        g = unpack2(acc3); ob[(size_t)6 * HW] = g.x * inv; ob[(size_t)7 * HW] = g.y * inv;
    }
}

// =========================================================================
extern "C" void kernel_launch(void* const* d_in, const int* in_sizes, int n_in,
                              void* d_out, int out_size)
{
    (void)in_sizes; (void)n_in; (void)out_size;
    const float* x    = (const float*)d_in[0];
    const float* wq   = (const float*)d_in[1];
    const float* wkv  = (const float*)d_in[2];
    const float* hrel = (const float*)d_in[3];
    const float* wrel = (const float*)d_in[4];
    float* out = (float*)d_out;

    cudaFuncSetAttribute(attn_kernel, cudaFuncAttributeMaxDynamicSharedMemorySize, SMEM_BYTES);

    qkv_gemm<<<dim3(128, 12, 4), 256>>>(x, wq, wkv);
    attn_kernel<<<dim3(NBLK, NHEAD, 4), 256, SMEM_BYTES>>>(hrel, wrel, out);
}

// round 17
// speedup vs baseline: 1.0016x; 1.0012x over previous
#include <cuda_runtime.h>
#include <cuda_bf16.h>
#include <cstdint>

typedef unsigned long long u64;

// ---------------- constants ----------------
#define NHEAD 8
#define DH 32
#define BLOCK 8
#define HALO 3
#define WIN 14          // BLOCK + 2*HALO
#define KK 196          // WIN*WIN
#define QN 64           // BLOCK*BLOCK
#define NBS 16          // blocks per side (128/8)
#define NBLK 256        // NBS*NBS
#define HW 16384        // 128*128
#define SCALE 0.17677669529663688f

// scratch: q in attention layout [b*8+head][blk][qp][d]
__device__ float g_q[4 * 8 * NBLK * QN * DH];          // 16.78M floats
// kv in spatial-major layout [b][y][x][ch512]; head h: k=ch[64h..64h+32), v=ch[64h+32..64h+64)
__device__ float g_kv[4 * 128 * 128 * 512];            // 33.55M floats

// ---------------- f32x2 helpers ----------------
__device__ __forceinline__ u64 pack2(float lo, float hi) {
    u64 r; asm("mov.b64 %0,{%1,%2};" : "=l"(r) : "f"(lo), "f"(hi)); return r;
}
__device__ __forceinline__ void fma2(u64& d, u64 a, u64 b) {
    asm("fma.rn.f32x2 %0,%1,%2,%0;" : "+l"(d) : "l"(a), "l"(b));
}
__device__ __forceinline__ float2 unpack2(u64 v) {
    float2 f; asm("mov.b64 {%0,%1},%2;" : "=f"(f.x), "=f"(f.y) : "l"(v)); return f;
}

// =========================================================================
// Kernel 1: fused QKV projection.  Y[768,16384] = W[768,256] @ X[256,16384]
// per batch.  Tile: 64 (o) x 128 (s), 256 threads, thread tile 8x4.
// =========================================================================
__global__ __launch_bounds__(256) void qkv_gemm(
    const float* __restrict__ x,
    const float* __restrict__ wq,
    const float* __restrict__ wkv)
{
    __shared__ float As[16][68];     // [k][o], padded
    __shared__ float Bs[16][128];    // [k][s]

    const int b      = blockIdx.z;
    const int tile_o = blockIdx.y * 64;
    const int tile_s = blockIdx.x * 128;
    const int tid    = threadIdx.x;
    const int tx     = tid & 31;     // s dir
    const int ty     = tid >> 5;     // o dir (warp id)

    // A-load mapping: 64 rows x 16 cols per tile
    const int arow = tid >> 2;              // 0..63
    const int acol = (tid & 3) << 2;        // 0,4,8,12
    const int oa   = tile_o + arow;
    const float* wrow = (oa < 256) ? (wq + (size_t)oa * 256)
                                   : (wkv + (size_t)(oa - 256) * 256);
    // B-load mapping: 16 rows x 128 cols
    const int brow = tid >> 4;              // 0..15
    const int bcol = (tid & 15) << 3;       // 0..120 step 8
    const float* xbase = x + ((size_t)b * 256 + brow) * HW + tile_s + bcol;

    u64 acc[4][4];
    #pragma unroll
    for (int i = 0; i < 4; i++)
        #pragma unroll
        for (int j = 0; j < 4; j++) acc[i][j] = 0ULL;

    for (int kt = 0; kt < 256; kt += 16) {
        float4 av = *(const float4*)(wrow + kt + acol);
        As[acol + 0][arow] = av.x;
        As[acol + 1][arow] = av.y;
        As[acol + 2][arow] = av.z;
        As[acol + 3][arow] = av.w;
        const float* xp = xbase + (size_t)kt * HW;
        float4 b0 = *(const float4*)(xp);
        float4 b1 = *(const float4*)(xp + 4);
        *(float4*)&Bs[brow][bcol]     = b0;
        *(float4*)&Bs[brow][bcol + 4] = b1;
        __syncthreads();

        #pragma unroll
        for (int k = 0; k < 16; k++) {
            const u64* a2 = (const u64*)&As[k][ty << 3];  // 16B-aligned (272B row stride)
            u64 A0 = a2[0], A1 = a2[1], A2 = a2[2], A3 = a2[3];
            float4 bv = *(const float4*)&Bs[k][tx << 2];
            u64 B0 = pack2(bv.x, bv.x);
            u64 B1 = pack2(bv.y, bv.y);
            u64 B2 = pack2(bv.z, bv.z);
            u64 B3 = pack2(bv.w, bv.w);
            fma2(acc[0][0], A0, B0); fma2(acc[1][0], A1, B0); fma2(acc[2][0], A2, B0); fma2(acc[3][0], A3, B0);
            fma2(acc[0][1], A0, B1); fma2(acc[1][1], A1, B1); fma2(acc[2][1], A2, B1); fma2(acc[3][1], A3, B1);
            fma2(acc[0][2], A0, B2); fma2(acc[1][2], A1, B2); fma2(acc[2][2], A2, B2); fma2(acc[3][2], A3, B2);
            fma2(acc[0][3], A0, B3); fma2(acc[1][3], A1, B3); fma2(acc[2][3], A2, B3); fma2(acc[3][3], A3, B3);
        }
        __syncthreads();
    }

    // epilogue: thread owns o = o0..o0+7 (within one head), s = s0..s0+3
    const int o0 = tile_o + (ty << 3);
    const int s0 = tile_s + (tx << 2);
    #pragma unroll
    for (int j = 0; j < 4; j++) {
        const int s = s0 + j;
        const int y = s >> 7, xx = s & 127;
        float2 f0 = unpack2(acc[0][j]);
        float2 f1 = unpack2(acc[1][j]);
        float2 f2 = unpack2(acc[2][j]);
        float2 f3 = unpack2(acc[3][j]);
        float4 lo = make_float4(f0.x, f0.y, f1.x, f1.y);
        float4 hi = make_float4(f2.x, f2.y, f3.x, f3.y);
        if (tile_o < 256) {
            const int head = o0 >> 5, d0 = o0 & 31;
            const int blkq = ((y >> 3) << 4) + (xx >> 3);
            const int qp   = ((y & 7) << 3) + (xx & 7);
            float* dst = g_q + ((((size_t)(b * 8 + head) * NBLK + blkq) << 6) + qp) * 32 + d0;
            *(float4*)dst       = lo;
            *(float4*)(dst + 4) = hi;
        } else {
            const int oc = o0 - 256;
            float* dst = g_kv + (((size_t)(b * 128 + y) * 128 + xx) << 9) + oc;
            *(float4*)dst       = lo;
            *(float4*)(dst + 4) = hi;
        }
    }
}

// =========================================================================
// Kernel 2: halo attention. One CTA per (b, head, block). 256 threads.
// =========================================================================
#define SMEM_FLOATS 33552
#define SMEM_BYTES  (SMEM_FLOATS * 4)

__global__ __launch_bounds__(256) void attn_kernel(
    const float* __restrict__ hrel,
    const float* __restrict__ wrel,
    float* __restrict__ out)
{
    extern __shared__ float sm[];
    float* qs = sm;            // 64 x 34   (stride 34 -> 8B aligned rows, conflict-free)
    float* ks = qs + 2176;     // 196 x 34
    float* vs = ks + 6664;     // 196 x 34
    float* P  = vs + 6664;     // 64 x 197  (stride 197 -> conflict-free scatter)
    float* qh = P  + 12608;    // 64 x 27
    float* qw = qh + 1728;     // 64 x 27
    float* sh = qw + 1728;     // 27 x 32
    float* sw = sh + 864;      // 27 x 32
    float* red = sw + 864;     // 256

    const int b = blockIdx.z, head = blockIdx.y, blk = blockIdx.x;
    const int tid = threadIdx.x;
    const int blky = blk >> 4, blkx = blk & 15;

    // ---- load q tile (contiguous 8KB) ----
    const float* qg = g_q + (((size_t)(b * 8 + head) * NBLK + blk) << 11);
    for (int i = tid; i < 2048; i += 256)
        qs[(i >> 5) * 34 + (i & 31)] = qg[i];
    // ---- rel tables ----
    for (int i = tid; i < 864; i += 256) { sh[i] = hrel[i]; sw[i] = wrel[i]; }
    // ---- gather K/V window (256B contiguous per position, zero halo OOB) ----
    const int y0 = blky * 8 - HALO, x0 = blkx * 8 - HALO;
    const float* kvb = g_kv + (size_t)b * 128 * 128 * 512 + head * 64;
    for (int i = tid; i < KK * 64; i += 256) {
        const int pos = i >> 6, ch = i & 63;
        const int kr = pos / 14, kc = pos - kr * 14;
        const int yy = y0 + kr, xx = x0 + kc;
        float v = 0.f;
        if ((unsigned)yy < 128u && (unsigned)xx < 128u)
            v = kvb[(((size_t)yy << 7) + xx) * 512 + ch];
        if (ch < 32) ks[pos * 34 + ch] = v;
        else         vs[pos * 34 + ch - 32] = v;
    }
    __syncthreads();

    // ---- rel-pos projections qh[qp][idx] = q . height_rel[idx], qw likewise ----
    for (int i = tid; i < 64 * 54; i += 256) {
        const int qp = i / 54, rr = i - qp * 54;
        const float* rel = (rr < 27) ? (sh + rr * 32) : (sw + (rr - 27) * 32);
        const float* qr = qs + qp * 34;
        float a = 0.f;
        #pragma unroll
        for (int d = 0; d < 32; d++) a += qr[d] * rel[d];
        if (rr < 27) qh[qp * 27 + rr] = a;
        else         qw[qp * 27 + rr - 27] = a;
    }
    __syncthreads();

    // ---- logits: thread = (qp, k-chunk of 49) ----
    {
        const int qp = tid & 63, chunk = tid >> 6;
        const int r = qp >> 3, c = qp & 7;
        const u64* q2 = (const u64*)(qs + qp * 34);
        u64 qa[16];
        #pragma unroll
        for (int j = 0; j < 16; j++) qa[j] = q2[j];
        const float* qhr = qh + qp * 27 + (13 - r);
        const float* qwr = qw + qp * 27 + (13 - c);
        float* prow = P + qp * 197;
        for (int kk = chunk; kk < KK; kk += 4) {
            const int kr = kk / 14, kc = kk - kr * 14;
            const u64* k2 = (const u64*)(ks + kk * 34);  // broadcast within warp
            u64 a0 = 0ULL, a1 = 0ULL, a2 = 0ULL, a3 = 0ULL;
            #pragma unroll
            for (int j = 0; j < 16; j += 4) {
                fma2(a0, qa[j],     k2[j]);
                fma2(a1, qa[j + 1], k2[j + 1]);
                fma2(a2, qa[j + 2], k2[j + 2]);
                fma2(a3, qa[j + 3], k2[j + 3]);
            }
            float2 f0 = unpack2(a0), f1 = unpack2(a1), f2 = unpack2(a2), f3 = unpack2(a3);
            const float dot = ((f0.x + f0.y) + (f1.x + f1.y)) + ((f2.x + f2.y) + (f3.x + f3.y));
            prow[kk] = dot * SCALE + qhr[kr] + qwr[kc];
        }
    }
    __syncthreads();

    // ---- softmax: 4 threads per q row, 49 keys each ----
    const int qpS = tid >> 2, q4 = tid & 3;
    {
        float* pr = P + qpS * 197 + q4 * 49;
        float m = -1e30f;
        for (int j = 0; j < 49; j++) m = fmaxf(m, pr[j]);
        red[tid] = m;
        __syncthreads();
        const float mm = fmaxf(fmaxf(red[qpS * 4], red[qpS * 4 + 1]),
                               fmaxf(red[qpS * 4 + 2], red[qpS * 4 + 3]));
        __syncthreads();
        float s = 0.f;
        for (int j = 0; j < 49; j++) { float e = __expf(pr[j] - mm); pr[j] = e; s += e; }
        red[tid] = s;
        __syncthreads();
    }
    const float denom = red[qpS * 4] + red[qpS * 4 + 1] + red[qpS * 4 + 2] + red[qpS * 4 + 3];
    const float inv = 1.0f / denom;

    // ---- AV: thread = (q row, 8 dv channels) ----
    {
        const int dv0 = q4 << 3;
        const float* pr = P + qpS * 197;
        u64 acc0 = 0ULL, acc1 = 0ULL, acc2 = 0ULL, acc3 = 0ULL;
        #pragma unroll 4
        for (int j = 0; j < KK; j++) {
            const float p = pr[j];
            const u64 p2 = pack2(p, p);
            const u64* vr = (const u64*)(vs + j * 34 + dv0);
            fma2(acc0, p2, vr[0]);
            fma2(acc1, p2, vr[1]);
            fma2(acc2, p2, vr[2]);
            fma2(acc3, p2, vr[3]);
        }
        const int rr = qpS >> 3, cc = qpS & 7;
        const int y = blky * 8 + rr, x = blkx * 8 + cc;
        float* ob = out + (((size_t)(b * 256) + head * 32 + dv0) * 128 + y) * 128 + x;
        float2 g;
        g = unpack2(acc0); ob[0]         = g.x * inv; ob[(size_t)1 * HW] = g.y * inv;
        g = unpack2(acc1); ob[(size_t)2 * HW] = g.x * inv; ob[(size_t)3 * HW] = g.y * inv;
        g = unpack2(acc2); ob[(size_t)4 * HW] = g.x * inv; ob[(size_t)5 * HW] = g.y * inv;
        g = unpack2(acc3); ob[(size_t)6 * HW] = g.x * inv; ob[(size_t)7 * HW] = g.y * inv;
    }
}

// =========================================================================
extern "C" void kernel_launch(void* const* d_in, const int* in_sizes, int n_in,
                              void* d_out, int out_size)
{
    (void)in_sizes; (void)n_in; (void)out_size;
    const float* x    = (const float*)d_in[0];
    const float* wq   = (const float*)d_in[1];
    const float* wkv  = (const float*)d_in[2];
    const float* hrel = (const float*)d_in[3];
    const float* wrel = (const float*)d_in[4];
    float* out = (float*)d_out;

    cudaFuncSetAttribute(attn_kernel, cudaFuncAttributeMaxDynamicSharedMemorySize, SMEM_BYTES);

    qkv_gemm<<<dim3(128, 12, 4), 256>>>(x, wq, wkv);
    attn_kernel<<<dim3(NBLK, NHEAD, 4), 256, SMEM_BYTES>>>(hrel, wrel, out);
}